// round 5
// baseline (speedup 1.0000x reference)
#include <cuda_runtime.h>
#include <cstdint>
#include <cstddef>

#define DI __device__ __forceinline__

namespace {
constexpr int IN_DIM  = 1024;
constexpr int MEM_DIM = 512;
constexpr int N_NODES = 100000;
constexpr int BATCH   = 65536;

constexpr int BM = 128, BN = 256, BK = 32;
constexpr int MT = BATCH / BM;     // 512
constexpr int NT = MEM_DIM / BN;   // 2
constexpr int KC = IN_DIM / BK;    // 32
constexpr int THREADS = 512;       // 16 warps: 2 (M) x 8 (N), warp tile 64x32

// smem: per buffer A[128 rows][128B] + B[256 rows][128B]; rows are 32 tf32 (one BK chunk),
// 16B units XOR-swizzled by (row&7) for conflict-free ldmatrix.
constexpr int SA_BYTES  = BM * 128;              // 16 KB
constexpr int SB_BYTES  = BN * 128;              // 32 KB
constexpr int BUF_BYTES = SA_BYTES + SB_BYTES;   // 48 KB
constexpr int SMEM_BYTES = 2 * BUF_BYTES;        // 96 KB
}  // namespace

// ---------------- base-ISA helpers (NO tcgen05 — target is plain sm_103) ----------------

DI uint32_t smem_u32(const void* p) {
    uint32_t a;
    asm("{ .reg .u64 t; cvta.to.shared.u64 t, %1; cvt.u32.u64 %0, t; }" : "=r"(a) : "l"(p));
    return a;
}

DI uint32_t f2tf32(float f) {   // round-to-nearest tf32 (unbiased — REQUIRED for accuracy)
    uint32_t r;
    asm("cvt.rna.tf32.f32 %0, %1;" : "=r"(r) : "f"(f));
    return r;
}

DI void ldsm_x4(uint32_t* r, uint32_t addr) {
    asm volatile("ldmatrix.sync.aligned.m8n8.x4.shared.b16 {%0,%1,%2,%3}, [%4];"
                 : "=r"(r[0]), "=r"(r[1]), "=r"(r[2]), "=r"(r[3]) : "r"(addr));
}

DI void mma_tf32(float* c, const uint32_t* a, const uint32_t* b) {
    asm volatile(
        "mma.sync.aligned.m16n8k8.row.col.f32.tf32.tf32.f32 "
        "{%0,%1,%2,%3}, {%4,%5,%6,%7}, {%8,%9}, {%0,%1,%2,%3};"
        : "+f"(c[0]), "+f"(c[1]), "+f"(c[2]), "+f"(c[3])
        : "r"(a[0]), "r"(a[1]), "r"(a[2]), "r"(a[3]), "r"(b[0]), "r"(b[1]));
}

DI void sts128(uint32_t addr, uint32_t x, uint32_t y, uint32_t z, uint32_t w) {
    asm volatile("st.shared.v4.b32 [%0], {%1,%2,%3,%4};"
                 :: "r"(addr), "r"(x), "r"(y), "r"(z), "r"(w));
}

// ---------------- Kernel 1: out = concat(entity_mem, rel_mem) * (t>1 ? t/(t+1) : 1) ----------------

__global__ void init_out_kernel(const float4* __restrict__ ent, const float4* __restrict__ rel,
                                const int* __restrict__ timep, float4* __restrict__ out) {
    const long long NODE4 = (long long)N_NODES * MEM_DIM / 4;
    const long long TOT4  = NODE4 + 500LL * MEM_DIM / 4;
    long long i = (long long)blockIdx.x * blockDim.x + threadIdx.x;
    if (i >= TOT4) return;
    int t = *timep;
    float s = (t > 1) ? (float)t / (float)(t + 1) : 1.0f;
    float4 v = (i < NODE4) ? ent[i] : rel[i - NODE4];
    v.x *= s; v.y *= s; v.z *= s; v.w *= s;
    out[i] = v;
}

// ---------------- Kernel 2: TF32 mma.sync GEMM + fused bias/scale + atomic scatter ----------------

__global__ void __launch_bounds__(THREADS, 1)
gemm_scatter_kernel(const float* __restrict__ nodes_emb, const float* __restrict__ rels_emb,
                    const int* __restrict__ nodes_ids, const int* __restrict__ rels_ids,
                    const float* __restrict__ W_node, const float* __restrict__ b_node,
                    const float* __restrict__ W_rel, const float* __restrict__ b_rel,
                    const int* __restrict__ timep, float* __restrict__ out) {
    extern __shared__ char smem[];
    const uint32_t sb = smem_u32(smem);
    const int tid = threadIdx.x;
    const int lane = tid & 31;
    const int wid = tid >> 5;
    const int wm = wid & 1;      // warp row (2)  -> 64 M rows each
    const int wn = wid >> 1;     // warp col (8)  -> 32 N cols each

    const bool is_rel = (blockIdx.x >= (unsigned)(MT * NT));
    const int bid = is_rel ? (int)blockIdx.x - MT * NT : (int)blockIdx.x;
    const int tile_n = bid & (NT - 1);
    const int tile_m = bid >> 1;

    const float* Aptr = is_rel ? rels_emb : nodes_emb;
    const float* Wptr = is_rel ? W_rel : W_node;
    const float* bias = is_rel ? b_rel : b_node;
    const int*   ids  = is_rel ? rels_ids : nodes_ids;
    float* outhalf = out + (is_rel ? (size_t)N_NODES * MEM_DIM : 0);

    const float* Abase = Aptr + (size_t)(tile_m * BM) * IN_DIM;
    const float* Wbase = Wptr + (size_t)(tile_n * BN) * IN_DIM;

    // ---- load-slot precompute (byte offsets to save registers) ----
    // A: 1024 16B-slots, 2/thread; B: 2048 slots, 4/thread. slot idx = j*512 + tid.
    uint32_t a_go[2], a_st[2];
#pragma unroll
    for (int j = 0; j < 2; ++j) {
        int idx = j * THREADS + tid;
        int row = idx >> 3, k4 = idx & 7;
        a_go[j] = (uint32_t)(row * IN_DIM + k4 * 4);                 // element offset
        a_st[j] = (uint32_t)(row * 128 + ((k4 ^ (row & 7)) << 4));   // byte offset in bufA
    }
    uint32_t b_go[4], b_st[4];
#pragma unroll
    for (int j = 0; j < 4; ++j) {
        int idx = j * THREADS + tid;
        int row = idx >> 3, k4 = idx & 7;
        b_go[j] = (uint32_t)(row * IN_DIM + k4 * 4);
        b_st[j] = (uint32_t)(SA_BYTES + row * 128 + ((k4 ^ (row & 7)) << 4));
    }

    // ---- ldmatrix address precompute ----
    // A frag (m16n8k8): lanes 0-7 -> rows +0..7 (k lo16B), 8-15 -> rows+8 (k lo),
    //                   16-23 -> rows+0..7 (k hi16B), 24-31 -> rows+8 (k hi)
    const int a_khi = lane >> 4;                      // 0/1
    uint32_t a_row128[4]; int a_r7[4];
#pragma unroll
    for (int mt = 0; mt < 4; ++mt) {
        int row = wm * 64 + mt * 16 + (lane & 7) + ((lane >> 3) & 1) * 8;
        a_row128[mt] = (uint32_t)(row * 128);
        a_r7[mt] = row & 7;
    }
    // B frag: lanes 0-7 -> n+0..7 (k lo), 8-15 -> n+0..7 (k hi), 16-23 -> n+8 (lo), 24-31 -> n+8 (hi)
    const int b_khi = (lane >> 3) & 1;
    uint32_t b_row128[2]; int b_r7[2];
#pragma unroll
    for (int np = 0; np < 2; ++np) {
        int row = wn * 32 + np * 16 + (lane & 7) + ((lane >> 4) & 1) * 8;
        b_row128[np] = (uint32_t)(SA_BYTES + row * 128);
        b_r7[np] = row & 7;
    }

    float C[4][4][4];
#pragma unroll
    for (int mt = 0; mt < 4; ++mt)
#pragma unroll
        for (int nt = 0; nt < 4; ++nt)
#pragma unroll
            for (int v = 0; v < 4; ++v) C[mt][nt][v] = 0.0f;

    auto kstep = [&](uint32_t bufbase, int ks) {
        uint32_t afr[4][4];
#pragma unroll
        for (int mt = 0; mt < 4; ++mt) {
            uint32_t addr = bufbase + a_row128[mt] + (uint32_t)(((2 * ks + a_khi) ^ a_r7[mt]) << 4);
            ldsm_x4(afr[mt], addr);
        }
#pragma unroll
        for (int np = 0; np < 2; ++np) {
            uint32_t bfr[4];
            uint32_t addr = bufbase + b_row128[np] + (uint32_t)(((2 * ks + b_khi) ^ b_r7[np]) << 4);
            ldsm_x4(bfr, addr);
#pragma unroll
            for (int mt = 0; mt < 4; ++mt) {
                mma_tf32(C[mt][2 * np],     afr[mt], bfr);
                mma_tf32(C[mt][2 * np + 1], afr[mt], bfr + 2);
            }
        }
    };

    // ---- prologue: fill buffer 0 with chunk 0 ----
    {
#pragma unroll
        for (int j = 0; j < 2; ++j) {
            float4 v = *reinterpret_cast<const float4*>(Abase + a_go[j]);
            sts128(sb + a_st[j], f2tf32(v.x), f2tf32(v.y), f2tf32(v.z), f2tf32(v.w));
        }
#pragma unroll
        for (int j = 0; j < 4; ++j) {
            float4 v = *reinterpret_cast<const float4*>(Wbase + b_go[j]);
            sts128(sb + b_st[j], f2tf32(v.x), f2tf32(v.y), f2tf32(v.z), f2tf32(v.w));
        }
    }
    __syncthreads();

    // ---- main loop: per chunk, 4 ksteps interleaved with next-chunk load/convert ----
    uint32_t buf = 0;
    for (int kc = 0; kc < KC; ++kc) {
        const uint32_t cur = sb + buf * (uint32_t)BUF_BYTES;
        const uint32_t nxt = sb + (buf ^ 1) * (uint32_t)BUF_BYTES;
        const bool has_next = (kc + 1 < KC);
        const int koff = (kc + 1) * BK;

        float4 ra[2], rb0[2], rb1[2];
        if (has_next) {
#pragma unroll
            for (int j = 0; j < 2; ++j)
                ra[j] = *reinterpret_cast<const float4*>(Abase + koff + a_go[j]);
        }
        kstep(cur, 0);
        if (has_next) {
#pragma unroll
            for (int j = 0; j < 2; ++j)
                sts128(nxt + a_st[j], f2tf32(ra[j].x), f2tf32(ra[j].y), f2tf32(ra[j].z), f2tf32(ra[j].w));
#pragma unroll
            for (int j = 0; j < 2; ++j)
                rb0[j] = *reinterpret_cast<const float4*>(Wbase + koff + b_go[j]);
        }
        kstep(cur, 1);
        if (has_next) {
#pragma unroll
            for (int j = 0; j < 2; ++j)
                sts128(nxt + b_st[j], f2tf32(rb0[j].x), f2tf32(rb0[j].y), f2tf32(rb0[j].z), f2tf32(rb0[j].w));
#pragma unroll
            for (int j = 0; j < 2; ++j)
                rb1[j] = *reinterpret_cast<const float4*>(Wbase + koff + b_go[j + 2]);
        }
        kstep(cur, 2);
        if (has_next) {
#pragma unroll
            for (int j = 0; j < 2; ++j)
                sts128(nxt + b_st[j + 2], f2tf32(rb1[j].x), f2tf32(rb1[j].y), f2tf32(rb1[j].z), f2tf32(rb1[j].w));
        }
        kstep(cur, 3);
        __syncthreads();
        buf ^= 1;
    }

    // ---- epilogue: out[id[m]] += (C + bias) / (t+1), atomic (RED) scatter ----
    const int t = *timep;
    const float inv = 1.0f / (float)(t + 1);
    const int g = lane >> 2;        // row within 8-group
    const int tg = lane & 3;        // col pair selector

    float* p[8];   // output row base pointers for the 8 M rows this thread owns
#pragma unroll
    for (int mt = 0; mt < 4; ++mt) {
        int r0 = tile_m * BM + wm * 64 + mt * 16 + g;
        p[2 * mt]     = outhalf + (size_t)ids[r0] * MEM_DIM;
        p[2 * mt + 1] = outhalf + (size_t)ids[r0 + 8] * MEM_DIM;
    }
#pragma unroll
    for (int nt = 0; nt < 4; ++nt) {
        const int c = tile_n * BN + wn * 32 + nt * 8 + tg * 2;
        const float2 bv = *reinterpret_cast<const float2*>(bias + c);
#pragma unroll
        for (int mt = 0; mt < 4; ++mt) {
            atomicAdd(p[2 * mt] + c,         (C[mt][nt][0] + bv.x) * inv);
            atomicAdd(p[2 * mt] + c + 1,     (C[mt][nt][1] + bv.y) * inv);
            atomicAdd(p[2 * mt + 1] + c,     (C[mt][nt][2] + bv.x) * inv);
            atomicAdd(p[2 * mt + 1] + c + 1, (C[mt][nt][3] + bv.y) * inv);
        }
    }
}

// ---------------- launch ----------------

extern "C" void kernel_launch(void* const* d_in, const int* in_sizes, int n_in,
                              void* d_out, int out_size) {
    const float* nodes_emb = (const float*)d_in[0];
    const float* rels_emb  = (const float*)d_in[1];
    const int*   nodes_ids = (const int*)d_in[2];
    const int*   rels_ids  = (const int*)d_in[3];
    const float* ent_mem   = (const float*)d_in[4];
    const float* rel_mem   = (const float*)d_in[5];
    const float* W_node    = (const float*)d_in[6];
    const float* b_node    = (const float*)d_in[7];
    const float* W_rel     = (const float*)d_in[8];
    const float* b_rel     = (const float*)d_in[9];
    const int*   timep     = (const int*)d_in[10];
    float* out = (float*)d_out;

    static bool attr_set = false;
    if (!attr_set) {
        cudaFuncSetAttribute(gemm_scatter_kernel,
                             cudaFuncAttributeMaxDynamicSharedMemorySize, SMEM_BYTES);
        attr_set = true;
    }

    // 1) out = scaled concat of memories
    const long long TOT4 = ((long long)N_NODES * MEM_DIM + 500LL * MEM_DIM) / 4;
    const int blocks = (int)((TOT4 + 255) / 256);
    init_out_kernel<<<blocks, 256>>>((const float4*)ent_mem, (const float4*)rel_mem, timep,
                                     (float4*)out);

    // 2) TF32 GEMM + scatter: nodes half then rels half in one grid
    gemm_scatter_kernel<<<2 * MT * NT, THREADS, SMEM_BYTES>>>(
        nodes_emb, rels_emb, nodes_ids, rels_ids,
        W_node, b_node, W_rel, b_rel, timep, out);
}

// round 6
// speedup vs baseline: 1.0107x; 1.0107x over previous
#include <cuda_runtime.h>
#include <cstdint>
#include <cstddef>

#define DI __device__ __forceinline__

namespace {
constexpr int IN_DIM  = 1024;
constexpr int MEM_DIM = 512;
constexpr int N_NODES = 100000;
constexpr int BATCH   = 65536;

constexpr int BM = 128, BN = 128, BK = 32;
constexpr int MT = BATCH / BM;     // 512
constexpr int NT = MEM_DIM / BN;   // 4
constexpr int KC = IN_DIM / BK;    // 32
constexpr int THREADS = 256;       // 8 warps: 2 (M) x 4 (N), warp tile 64x32

// smem per buffer: A[128 rows][128B] + B[128 rows][128B]; a row = 32 tf32 (one BK chunk),
// 16B units XOR-swizzled by (row&7) for conflict-free ldmatrix.
constexpr int SA_BYTES  = BM * 128;              // 16 KB
constexpr int SB_BYTES  = BN * 128;              // 16 KB
constexpr int BUF_BYTES = SA_BYTES + SB_BYTES;   // 32 KB
constexpr int SMEM_BYTES = 2 * BUF_BYTES;        // 64 KB  (2 CTAs/SM -> 128 KB/SM)
}  // namespace

// ---------------- base-ISA helpers (NO tcgen05 — target is plain sm_103) ----------------

DI uint32_t smem_u32(const void* p) {
    uint32_t a;
    asm("{ .reg .u64 t; cvta.to.shared.u64 t, %1; cvt.u32.u64 %0, t; }" : "=r"(a) : "l"(p));
    return a;
}

DI uint32_t f2tf32(float f) {   // round-to-nearest tf32 (unbiased — REQUIRED for accuracy)
    uint32_t r;
    asm("cvt.rna.tf32.f32 %0, %1;" : "=r"(r) : "f"(f));
    return r;
}

DI void ldsm_x4(uint32_t* r, uint32_t addr) {
    asm volatile("ldmatrix.sync.aligned.m8n8.x4.shared.b16 {%0,%1,%2,%3}, [%4];"
                 : "=r"(r[0]), "=r"(r[1]), "=r"(r[2]), "=r"(r[3]) : "r"(addr));
}

DI void mma_tf32(float* c, const uint32_t* a, const uint32_t* b) {
    asm volatile(
        "mma.sync.aligned.m16n8k8.row.col.f32.tf32.tf32.f32 "
        "{%0,%1,%2,%3}, {%4,%5,%6,%7}, {%8,%9}, {%0,%1,%2,%3};"
        : "+f"(c[0]), "+f"(c[1]), "+f"(c[2]), "+f"(c[3])
        : "r"(a[0]), "r"(a[1]), "r"(a[2]), "r"(a[3]), "r"(b[0]), "r"(b[1]));
}

DI void sts128(uint32_t addr, uint32_t x, uint32_t y, uint32_t z, uint32_t w) {
    asm volatile("st.shared.v4.b32 [%0], {%1,%2,%3,%4};"
                 :: "r"(addr), "r"(x), "r"(y), "r"(z), "r"(w));
}

// ---------------- Kernel 1: out = concat(entity_mem, rel_mem) * (t>1 ? t/(t+1) : 1) ----------------

__global__ void init_out_kernel(const float4* __restrict__ ent, const float4* __restrict__ rel,
                                const int* __restrict__ timep, float4* __restrict__ out) {
    const long long NODE4 = (long long)N_NODES * MEM_DIM / 4;
    const long long TOT4  = NODE4 + 500LL * MEM_DIM / 4;
    long long i = (long long)blockIdx.x * blockDim.x + threadIdx.x;
    if (i >= TOT4) return;
    int t = *timep;
    float s = (t > 1) ? (float)t / (float)(t + 1) : 1.0f;
    float4 v = (i < NODE4) ? ent[i] : rel[i - NODE4];
    v.x *= s; v.y *= s; v.z *= s; v.w *= s;
    out[i] = v;
}

// ---------------- Kernel 2: TF32 mma.sync GEMM + fused bias/scale + atomic scatter ----------------

__global__ void __launch_bounds__(THREADS, 2)
gemm_scatter_kernel(const float* __restrict__ nodes_emb, const float* __restrict__ rels_emb,
                    const int* __restrict__ nodes_ids, const int* __restrict__ rels_ids,
                    const float* __restrict__ W_node, const float* __restrict__ b_node,
                    const float* __restrict__ W_rel, const float* __restrict__ b_rel,
                    const int* __restrict__ timep, float* __restrict__ out) {
    extern __shared__ char smem[];
    const uint32_t sb = smem_u32(smem);
    const int tid = threadIdx.x;
    const int lane = tid & 31;
    const int wid = tid >> 5;
    const int wm = wid & 1;      // warp row (2)  -> 64 M rows each
    const int wn = wid >> 1;     // warp col (4)  -> 32 N cols each

    const bool is_rel = (blockIdx.x >= (unsigned)(MT * NT));
    const int bid = is_rel ? (int)blockIdx.x - MT * NT : (int)blockIdx.x;
    const int tile_n = bid & (NT - 1);
    const int tile_m = bid >> 2;

    const float* Aptr = is_rel ? rels_emb : nodes_emb;
    const float* Wptr = is_rel ? W_rel : W_node;
    const float* bias = is_rel ? b_rel : b_node;
    const int*   ids  = is_rel ? rels_ids : nodes_ids;
    float* outhalf = out + (is_rel ? (size_t)N_NODES * MEM_DIM : 0);

    const float* Abase = Aptr + (size_t)(tile_m * BM) * IN_DIM;
    const float* Wbase = Wptr + (size_t)(tile_n * BN) * IN_DIM;

    // ---- load-slot precompute ----
    // A: 1024 16B-slots, 4/thread; B: 1024 slots, 4/thread. slot idx = j*256 + tid.
    uint32_t a_go[4], a_st[4], b_st[4];
#pragma unroll
    for (int j = 0; j < 4; ++j) {
        int idx = j * THREADS + tid;
        int row = idx >> 3, k4 = idx & 7;
        a_go[j] = (uint32_t)(row * IN_DIM + k4 * 4);                 // element offset (A and B share shape)
        a_st[j] = (uint32_t)(row * 128 + ((k4 ^ (row & 7)) << 4));   // byte offset in bufA
        b_st[j] = (uint32_t)(SA_BYTES) + a_st[j];                    // same pattern in bufB
    }

    // ---- ldmatrix address precompute ----
    const int a_khi = lane >> 4;                      // 0/1 (16B half of the k chunk-step)
    uint32_t a_row128[4]; int a_r7[4];
#pragma unroll
    for (int mt = 0; mt < 4; ++mt) {
        int row = wm * 64 + mt * 16 + (lane & 7) + ((lane >> 3) & 1) * 8;
        a_row128[mt] = (uint32_t)(row * 128);
        a_r7[mt] = row & 7;
    }
    const int b_khi = (lane >> 3) & 1;
    uint32_t b_row128[2]; int b_r7[2];
#pragma unroll
    for (int np = 0; np < 2; ++np) {
        int row = wn * 32 + np * 16 + (lane & 7) + ((lane >> 4) & 1) * 8;
        b_row128[np] = (uint32_t)(SA_BYTES + row * 128);
        b_r7[np] = row & 7;
    }

    float C[4][4][4];
#pragma unroll
    for (int mt = 0; mt < 4; ++mt)
#pragma unroll
        for (int nt = 0; nt < 4; ++nt)
#pragma unroll
            for (int v = 0; v < 4; ++v) C[mt][nt][v] = 0.0f;

    auto kstep = [&](uint32_t bufbase, int ks) {
        uint32_t afr[4][4];
#pragma unroll
        for (int mt = 0; mt < 4; ++mt) {
            uint32_t addr = bufbase + a_row128[mt] + (uint32_t)(((2 * ks + a_khi) ^ a_r7[mt]) << 4);
            ldsm_x4(afr[mt], addr);
        }
#pragma unroll
        for (int np = 0; np < 2; ++np) {
            uint32_t bfr[4];
            uint32_t addr = bufbase + b_row128[np] + (uint32_t)(((2 * ks + b_khi) ^ b_r7[np]) << 4);
            ldsm_x4(bfr, addr);
#pragma unroll
            for (int mt = 0; mt < 4; ++mt) {
                mma_tf32(C[mt][2 * np],     afr[mt], bfr);
                mma_tf32(C[mt][2 * np + 1], afr[mt], bfr + 2);
            }
        }
    };

    // ---- prologue: fill buffer 0 with chunk 0 ----
    {
#pragma unroll
        for (int j = 0; j < 4; ++j) {
            float4 v = *reinterpret_cast<const float4*>(Abase + a_go[j]);
            sts128(sb + a_st[j], f2tf32(v.x), f2tf32(v.y), f2tf32(v.z), f2tf32(v.w));
        }
#pragma unroll
        for (int j = 0; j < 4; ++j) {
            float4 v = *reinterpret_cast<const float4*>(Wbase + a_go[j]);
            sts128(sb + b_st[j], f2tf32(v.x), f2tf32(v.y), f2tf32(v.z), f2tf32(v.w));
        }
    }
    __syncthreads();

    // ---- main loop: per chunk, 4 ksteps interleaved with next-chunk load/convert ----
    uint32_t buf = 0;
    for (int kc = 0; kc < KC; ++kc) {
        const uint32_t cur = sb + buf * (uint32_t)BUF_BYTES;
        const uint32_t nxt = sb + (buf ^ 1) * (uint32_t)BUF_BYTES;
        const bool has_next = (kc + 1 < KC);
        const int koff = (kc + 1) * BK;

        float4 ra[4], rb0[2], rb1[2];
        if (has_next) {
#pragma unroll
            for (int j = 0; j < 4; ++j)
                ra[j] = *reinterpret_cast<const float4*>(Abase + koff + a_go[j]);
        }
        kstep(cur, 0);
        if (has_next) {
#pragma unroll
            for (int j = 0; j < 4; ++j)
                sts128(nxt + a_st[j], f2tf32(ra[j].x), f2tf32(ra[j].y), f2tf32(ra[j].z), f2tf32(ra[j].w));
#pragma unroll
            for (int j = 0; j < 2; ++j)
                rb0[j] = *reinterpret_cast<const float4*>(Wbase + koff + a_go[j]);
        }
        kstep(cur, 1);
        if (has_next) {
#pragma unroll
            for (int j = 0; j < 2; ++j)
                sts128(nxt + b_st[j], f2tf32(rb0[j].x), f2tf32(rb0[j].y), f2tf32(rb0[j].z), f2tf32(rb0[j].w));
#pragma unroll
            for (int j = 0; j < 2; ++j)
                rb1[j] = *reinterpret_cast<const float4*>(Wbase + koff + a_go[j + 2]);
        }
        kstep(cur, 2);
        if (has_next) {
#pragma unroll
            for (int j = 0; j < 2; ++j)
                sts128(nxt + b_st[j + 2], f2tf32(rb1[j].x), f2tf32(rb1[j].y), f2tf32(rb1[j].z), f2tf32(rb1[j].w));
        }
        kstep(cur, 3);
        __syncthreads();
        buf ^= 1;
    }

    // ---- epilogue: out[id[m]] += (C + bias) / (t+1), atomic (RED) scatter ----
    const int t = *timep;
    const float inv = 1.0f / (float)(t + 1);
    const int g = lane >> 2;        // row within 8-group
    const int tg = lane & 3;        // col pair selector

    float* p[8];
#pragma unroll
    for (int mt = 0; mt < 4; ++mt) {
        int r0 = tile_m * BM + wm * 64 + mt * 16 + g;
        p[2 * mt]     = outhalf + (size_t)ids[r0] * MEM_DIM;
        p[2 * mt + 1] = outhalf + (size_t)ids[r0 + 8] * MEM_DIM;
    }
#pragma unroll
    for (int nt = 0; nt < 4; ++nt) {
        const int c = tile_n * BN + wn * 32 + nt * 8 + tg * 2;
        const float2 bv = *reinterpret_cast<const float2*>(bias + c);
#pragma unroll
        for (int mt = 0; mt < 4; ++mt) {
            atomicAdd(p[2 * mt] + c,         (C[mt][nt][0] + bv.x) * inv);
            atomicAdd(p[2 * mt] + c + 1,     (C[mt][nt][1] + bv.y) * inv);
            atomicAdd(p[2 * mt + 1] + c,     (C[mt][nt][2] + bv.x) * inv);
            atomicAdd(p[2 * mt + 1] + c + 1, (C[mt][nt][3] + bv.y) * inv);
        }
    }
}

// ---------------- launch ----------------

extern "C" void kernel_launch(void* const* d_in, const int* in_sizes, int n_in,
                              void* d_out, int out_size) {
    const float* nodes_emb = (const float*)d_in[0];
    const float* rels_emb  = (const float*)d_in[1];
    const int*   nodes_ids = (const int*)d_in[2];
    const int*   rels_ids  = (const int*)d_in[3];
    const float* ent_mem   = (const float*)d_in[4];
    const float* rel_mem   = (const float*)d_in[5];
    const float* W_node    = (const float*)d_in[6];
    const float* b_node    = (const float*)d_in[7];
    const float* W_rel     = (const float*)d_in[8];
    const float* b_rel     = (const float*)d_in[9];
    const int*   timep     = (const int*)d_in[10];
    float* out = (float*)d_out;

    static bool attr_set = false;
    if (!attr_set) {
        cudaFuncSetAttribute(gemm_scatter_kernel,
                             cudaFuncAttributeMaxDynamicSharedMemorySize, SMEM_BYTES);
        attr_set = true;
    }

    // 1) out = scaled concat of memories
    const long long TOT4 = ((long long)N_NODES * MEM_DIM + 500LL * MEM_DIM) / 4;
    const int blocks = (int)((TOT4 + 255) / 256);
    init_out_kernel<<<blocks, 256>>>((const float4*)ent_mem, (const float4*)rel_mem, timep,
                                     (float4*)out);

    // 2) TF32 GEMM + scatter: nodes half then rels half in one grid (2 CTAs/SM)
    gemm_scatter_kernel<<<2 * MT * NT, THREADS, SMEM_BYTES>>>(
        nodes_emb, rels_emb, nodes_ids, rels_ids,
        W_node, b_node, W_rel, b_rel, timep, out);
}

// round 7
// speedup vs baseline: 1.2970x; 1.2833x over previous
#include <cuda_runtime.h>
#include <cstdint>
#include <cstddef>

#define DI __device__ __forceinline__

namespace {
constexpr int IN_DIM  = 1024;
constexpr int MEM_DIM = 512;
constexpr int N_NODES = 100000;
constexpr int BATCH   = 65536;

constexpr int BM = 128, BN = 256, BK = 32;
constexpr int MT = BATCH / BM;     // 512
constexpr int NT = MEM_DIM / BN;   // 2
constexpr int KC = IN_DIM / BK;    // 32
constexpr int THREADS = 256;       // 8 warps: 2 (M) x 4 (N), warp tile 64x64
constexpr int STAGES = 4;

// smem per stage: A[128 rows][128B] + B[256 rows][128B]; a row = 32 fp32 (one BK chunk),
// 16B units XOR-swizzled by (row&7) for conflict-free ldmatrix.
constexpr int SA_BYTES    = BM * 128;               // 16 KB
constexpr int SB_BYTES    = BN * 128;               // 32 KB
constexpr int STAGE_BYTES = SA_BYTES + SB_BYTES;    // 48 KB
constexpr int SMEM_BYTES  = STAGES * STAGE_BYTES;   // 192 KB
}  // namespace

// ---------------- base-ISA helpers (NO tcgen05 — target is plain sm_103) ----------------

DI uint32_t smem_u32(const void* p) {
    uint32_t a;
    asm("{ .reg .u64 t; cvta.to.shared.u64 t, %1; cvt.u32.u64 %0, t; }" : "=r"(a) : "l"(p));
    return a;
}

DI uint32_t f2tf32(uint32_t fbits) {   // round-to-nearest tf32 on raw fp32 bits
    uint32_t r;
    asm("cvt.rna.tf32.f32 %0, %1;" : "=r"(r) : "r"(fbits));
    return r;
}

DI void ldsm_x4(uint32_t* r, uint32_t addr) {
    asm volatile("ldmatrix.sync.aligned.m8n8.x4.shared.b16 {%0,%1,%2,%3}, [%4];"
                 : "=r"(r[0]), "=r"(r[1]), "=r"(r[2]), "=r"(r[3]) : "r"(addr));
}

DI void mma_tf32(float* c, const uint32_t* a, const uint32_t* b) {
    asm volatile(
        "mma.sync.aligned.m16n8k8.row.col.f32.tf32.tf32.f32 "
        "{%0,%1,%2,%3}, {%4,%5,%6,%7}, {%8,%9}, {%0,%1,%2,%3};"
        : "+f"(c[0]), "+f"(c[1]), "+f"(c[2]), "+f"(c[3])
        : "r"(a[0]), "r"(a[1]), "r"(a[2]), "r"(a[3]), "r"(b[0]), "r"(b[1]));
}

DI void cp_async16(uint32_t smem_addr, const void* gptr) {
    asm volatile("cp.async.cg.shared.global [%0], [%1], 16;"
                 :: "r"(smem_addr), "l"(gptr));
}
DI void cp_commit() { asm volatile("cp.async.commit_group;"); }
DI void cp_wait2()  { asm volatile("cp.async.wait_group 2;"); }

// ---------------- Kernel 1: out = concat(entity_mem, rel_mem) * (t>1 ? t/(t+1) : 1) ----------------

__global__ void init_out_kernel(const float4* __restrict__ ent, const float4* __restrict__ rel,
                                const int* __restrict__ timep, float4* __restrict__ out) {
    const long long NODE4 = (long long)N_NODES * MEM_DIM / 4;
    const long long TOT4  = NODE4 + 500LL * MEM_DIM / 4;
    long long i = (long long)blockIdx.x * blockDim.x + threadIdx.x;
    if (i >= TOT4) return;
    int t = *timep;
    float s = (t > 1) ? (float)t / (float)(t + 1) : 1.0f;
    float4 v = (i < NODE4) ? ent[i] : rel[i - NODE4];
    v.x *= s; v.y *= s; v.z *= s; v.w *= s;
    out[i] = v;
}

// ---------------- Kernel 2: TF32 mma.sync GEMM (cp.async 4-stage) + atomic scatter ----------------

__global__ void __launch_bounds__(THREADS, 1)
gemm_scatter_kernel(const float* __restrict__ nodes_emb, const float* __restrict__ rels_emb,
                    const int* __restrict__ nodes_ids, const int* __restrict__ rels_ids,
                    const float* __restrict__ W_node, const float* __restrict__ b_node,
                    const float* __restrict__ W_rel, const float* __restrict__ b_rel,
                    const int* __restrict__ timep, float* __restrict__ out) {
    extern __shared__ char smem[];
    const uint32_t sb = smem_u32(smem);
    const int tid = threadIdx.x;
    const int lane = tid & 31;
    const int wid = tid >> 5;
    const int wm = wid & 1;      // warp row (2)  -> 64 M rows each
    const int wn = wid >> 1;     // warp col (4)  -> 64 N cols each

    const bool is_rel = (blockIdx.x >= (unsigned)(MT * NT));
    const int bid = is_rel ? (int)blockIdx.x - MT * NT : (int)blockIdx.x;
    const int tile_n = bid & (NT - 1);
    const int tile_m = bid >> 1;

    const float* Aptr = is_rel ? rels_emb : nodes_emb;
    const float* Wptr = is_rel ? W_rel : W_node;
    const float* bias = is_rel ? b_rel : b_node;
    const int*   ids  = is_rel ? rels_ids : nodes_ids;
    float* outhalf = out + (is_rel ? (size_t)N_NODES * MEM_DIM : 0);

    const float* Abase = Aptr + (size_t)(tile_m * BM) * IN_DIM;
    const float* Wbase = Wptr + (size_t)(tile_n * BN) * IN_DIM;

    // ---- cp.async slot precompute ----
    // A: 1024 16B-slots, 4/thread; B: 2048 slots, 8/thread. slot idx = j*256 + tid.
    const float* a_gp[4]; uint32_t a_st[4];
#pragma unroll
    for (int j = 0; j < 4; ++j) {
        int idx = j * THREADS + tid;
        int row = idx >> 3, k4 = idx & 7;
        a_gp[j] = Abase + (size_t)row * IN_DIM + k4 * 4;
        a_st[j] = (uint32_t)(row * 128 + ((k4 ^ (row & 7)) << 4));
    }
    const float* b_gp[8]; uint32_t b_st[8];
#pragma unroll
    for (int j = 0; j < 8; ++j) {
        int idx = j * THREADS + tid;
        int row = idx >> 3, k4 = idx & 7;
        b_gp[j] = Wbase + (size_t)row * IN_DIM + k4 * 4;
        b_st[j] = (uint32_t)(SA_BYTES + row * 128 + ((k4 ^ (row & 7)) << 4));
    }

    auto issue_chunk = [&](int kc) {   // always commits (empty groups keep wait arithmetic uniform)
        if (kc < KC) {
            const int koff = kc * BK;
            const uint32_t stg = sb + (uint32_t)(kc & (STAGES - 1)) * STAGE_BYTES;
#pragma unroll
            for (int j = 0; j < 4; ++j) cp_async16(stg + a_st[j], a_gp[j] + koff);
#pragma unroll
            for (int j = 0; j < 8; ++j) cp_async16(stg + b_st[j], b_gp[j] + koff);
        }
        cp_commit();
    };

    // ---- ldmatrix address precompute (same mapping as the validated R4 kernel) ----
    const int a_khi = lane >> 4;
    uint32_t a_row128[4]; int a_r7[4];
#pragma unroll
    for (int mt = 0; mt < 4; ++mt) {
        int row = wm * 64 + mt * 16 + (lane & 7) + ((lane >> 3) & 1) * 8;
        a_row128[mt] = (uint32_t)(row * 128);
        a_r7[mt] = row & 7;
    }
    const int b_khi = (lane >> 3) & 1;
    uint32_t b_row128[4]; int b_r7[4];
#pragma unroll
    for (int np = 0; np < 4; ++np) {
        int row = wn * 64 + np * 16 + (lane & 7) + ((lane >> 4) & 1) * 8;
        b_row128[np] = (uint32_t)(SA_BYTES + row * 128);
        b_r7[np] = row & 7;
    }

    float C[4][8][4];
#pragma unroll
    for (int mt = 0; mt < 4; ++mt)
#pragma unroll
        for (int nt = 0; nt < 8; ++nt)
#pragma unroll
            for (int v = 0; v < 4; ++v) C[mt][nt][v] = 0.0f;

    // ---- prologue: stages 0..2 in flight ----
    issue_chunk(0);
    issue_chunk(1);
    issue_chunk(2);

    // ---- main loop ----
    for (int kc = 0; kc < KC; ++kc) {
        cp_wait2();          // chunk kc's group complete (<=2 newer groups outstanding)
        __syncthreads();     // all warps: data visible; stage (kc+3)%4 fully consumed (read at kc-1)
        issue_chunk(kc + 3); // fire-and-forget, ~3 chunks of lead time

        const uint32_t cur = sb + (uint32_t)(kc & (STAGES - 1)) * STAGE_BYTES;
#pragma unroll
        for (int ks = 0; ks < 4; ++ks) {
            uint32_t afr[4][4];
#pragma unroll
            for (int mt = 0; mt < 4; ++mt) {
                uint32_t addr = cur + a_row128[mt] + (uint32_t)(((2 * ks + a_khi) ^ a_r7[mt]) << 4);
                ldsm_x4(afr[mt], addr);
#pragma unroll
                for (int v = 0; v < 4; ++v) afr[mt][v] = f2tf32(afr[mt][v]);
            }
#pragma unroll
            for (int np = 0; np < 4; ++np) {
                uint32_t bfr[4];
                uint32_t addr = cur + b_row128[np] + (uint32_t)(((2 * ks + b_khi) ^ b_r7[np]) << 4);
                ldsm_x4(bfr, addr);
#pragma unroll
                for (int v = 0; v < 4; ++v) bfr[v] = f2tf32(bfr[v]);
#pragma unroll
                for (int mt = 0; mt < 4; ++mt) {
                    mma_tf32(C[mt][2 * np],     afr[mt], bfr);
                    mma_tf32(C[mt][2 * np + 1], afr[mt], bfr + 2);
                }
            }
        }
        __syncthreads();     // done reading stage kc%4 before iteration kc+1 overwrites stage (kc+4)%4
    }

    // ---- epilogue: out[id[m]] += (C + bias) / (t+1), atomic (RED) scatter ----
    const int t = *timep;
    const float inv = 1.0f / (float)(t + 1);
    const int g = lane >> 2;
    const int tg = lane & 3;

    float* p[8];
#pragma unroll
    for (int mt = 0; mt < 4; ++mt) {
        int r0 = tile_m * BM + wm * 64 + mt * 16 + g;
        p[2 * mt]     = outhalf + (size_t)ids[r0] * MEM_DIM;
        p[2 * mt + 1] = outhalf + (size_t)ids[r0 + 8] * MEM_DIM;
    }
#pragma unroll
    for (int nt = 0; nt < 8; ++nt) {
        const int c = tile_n * BN + wn * 64 + nt * 8 + tg * 2;
        const float2 bv = *reinterpret_cast<const float2*>(bias + c);
#pragma unroll
        for (int mt = 0; mt < 4; ++mt) {
            atomicAdd(p[2 * mt] + c,         (C[mt][nt][0] + bv.x) * inv);
            atomicAdd(p[2 * mt] + c + 1,     (C[mt][nt][1] + bv.y) * inv);
            atomicAdd(p[2 * mt + 1] + c,     (C[mt][nt][2] + bv.x) * inv);
            atomicAdd(p[2 * mt + 1] + c + 1, (C[mt][nt][3] + bv.y) * inv);
        }
    }
}

// ---------------- launch ----------------

extern "C" void kernel_launch(void* const* d_in, const int* in_sizes, int n_in,
                              void* d_out, int out_size) {
    const float* nodes_emb = (const float*)d_in[0];
    const float* rels_emb  = (const float*)d_in[1];
    const int*   nodes_ids = (const int*)d_in[2];
    const int*   rels_ids  = (const int*)d_in[3];
    const float* ent_mem   = (const float*)d_in[4];
    const float* rel_mem   = (const float*)d_in[5];
    const float* W_node    = (const float*)d_in[6];
    const float* b_node    = (const float*)d_in[7];
    const float* W_rel     = (const float*)d_in[8];
    const float* b_rel     = (const float*)d_in[9];
    const int*   timep     = (const int*)d_in[10];
    float* out = (float*)d_out;

    static bool attr_set = false;
    if (!attr_set) {
        cudaFuncSetAttribute(gemm_scatter_kernel,
                             cudaFuncAttributeMaxDynamicSharedMemorySize, SMEM_BYTES);
        attr_set = true;
    }

    // 1) out = scaled concat of memories
    const long long TOT4 = ((long long)N_NODES * MEM_DIM + 500LL * MEM_DIM) / 4;
    const int blocks = (int)((TOT4 + 255) / 256);
    init_out_kernel<<<blocks, 256>>>((const float4*)ent_mem, (const float4*)rel_mem, timep,
                                     (float4*)out);

    // 2) TF32 GEMM + scatter: nodes half then rels half in one grid
    gemm_scatter_kernel<<<2 * MT * NT, THREADS, SMEM_BYTES>>>(
        nodes_emb, rels_emb, nodes_ids, rels_ids,
        W_node, b_node, W_rel, b_rel, timep, out);
}